// round 1
// baseline (speedup 1.0000x reference)
#include <cuda_runtime.h>

// 256 transformation matrices, 4x4 f32 each = 16 KB scratch.
__device__ float4 g_WM[256 * 4];

__global__ void build_wm_kernel(const float* __restrict__ aW,
                                const float* __restrict__ uW,
                                const float* __restrict__ tW) {
    int n = blockIdx.x * blockDim.x + threadIdx.x;
    if (n >= 256) return;

    float a = aW[n];
    // sigmoid then normalize
    float ux = 1.0f / (1.0f + expf(-uW[n * 3 + 0]));
    float uy = 1.0f / (1.0f + expf(-uW[n * 3 + 1]));
    float uz = 1.0f / (1.0f + expf(-uW[n * 3 + 2]));
    float inv = rsqrtf(ux * ux + uy * uy + uz * uz);
    ux *= inv; uy *= inv; uz *= inv;

    float s = sinf(a);
    float c = cosf(a);

    // R = K*sin + (I - uuT)*cos + uuT
    // K = [[0,-uz,uy],[uz,0,-ux],[-uy,ux,0]]
    float r00 = (1.0f - ux * ux) * c + ux * ux;
    float r01 = -uz * s - ux * uy * c + ux * uy;
    float r02 =  uy * s - ux * uz * c + ux * uz;
    float r10 =  uz * s - ux * uy * c + ux * uy;
    float r11 = (1.0f - uy * uy) * c + uy * uy;
    float r12 = -ux * s - uy * uz * c + uy * uz;
    float r20 = -uy * s - ux * uz * c + ux * uz;
    float r21 =  ux * s - uy * uz * c + uy * uz;
    float r22 = (1.0f - uz * uz) * c + uz * uz;

    float t0 = tW[n * 3 + 0];
    float t1 = tW[n * 3 + 1];
    float t2 = tW[n * 3 + 2];

    g_WM[n * 4 + 0] = make_float4(r00, r01, r02, t0);
    g_WM[n * 4 + 1] = make_float4(r10, r11, r12, t1);
    g_WM[n * 4 + 2] = make_float4(r20, r21, r22, t2);
    g_WM[n * 4 + 3] = make_float4(0.0f, 0.0f, 0.0f, 1.0f);
}

// One thread per output row (b, n, i): out_row = sum_k I_row[k] * WM[n][k][:]
__global__ void __launch_bounds__(256) apply_kernel(const float4* __restrict__ I,
                                                    float4* __restrict__ O,
                                                    int total_rows) {
    int idx = blockIdx.x * blockDim.x + threadIdx.x;
    if (idx >= total_rows) return;

    int n = (idx >> 2) & 255;  // row index: ((b*256 + n)*4 + i)

    float4 v = I[idx];
    const float4* W = &g_WM[n * 4];
    float4 r0 = __ldg(W + 0);
    float4 r1 = __ldg(W + 1);
    float4 r2 = __ldg(W + 2);
    float4 r3 = __ldg(W + 3);

    float4 o;
    o.x = fmaf(v.x, r0.x, fmaf(v.y, r1.x, fmaf(v.z, r2.x, v.w * r3.x)));
    o.y = fmaf(v.x, r0.y, fmaf(v.y, r1.y, fmaf(v.z, r2.y, v.w * r3.y)));
    o.z = fmaf(v.x, r0.z, fmaf(v.y, r1.z, fmaf(v.z, r2.z, v.w * r3.z)));
    o.w = fmaf(v.x, r0.w, fmaf(v.y, r1.w, fmaf(v.z, r2.w, v.w * r3.w)));

    O[idx] = o;
}

extern "C" void kernel_launch(void* const* d_in, const int* in_sizes, int n_in,
                              void* d_out, int out_size) {
    const float* I  = (const float*)d_in[0];
    const float* aW = (const float*)d_in[1];
    const float* uW = (const float*)d_in[2];
    const float* tW = (const float*)d_in[3];
    float* O = (float*)d_out;

    build_wm_kernel<<<1, 256>>>(aW, uW, tW);

    int total_rows = in_sizes[0] / 4;  // 4096*256*4 = 4194304 rows of float4
    int threads = 256;
    int blocks = (total_rows + threads - 1) / threads;
    apply_kernel<<<blocks, threads>>>((const float4*)I, (float4*)O, total_rows);
}

// round 2
// speedup vs baseline: 1.0237x; 1.0237x over previous
#include <cuda_runtime.h>

// Fused kernel:
//  - grid = (BATCH/ITER) * 2 blocks of 512 threads
//  - block covers half the N_IN range (128 matrices) for ITER consecutive batches
//  - prologue: threads 0..127 build their WM matrix into smem (Rodrigues)
//  - main: each thread owns one (n, row) pair; WM rows cached in registers;
//          streams ITER batches with 1 LDG.128 + 16 FFMA + 1 STG.128 per batch.

constexpr int N_IN  = 256;
constexpr int BATCH = 4096;
constexpr int ITER  = 8;
constexpr int TPB   = 512;           // 128 matrices * 4 rows
constexpr int HALF  = 128;           // matrices per block

__global__ void __launch_bounds__(TPB) fused_kernel(
    const float4* __restrict__ I,
    const float*  __restrict__ aW,
    const float*  __restrict__ uW,
    const float*  __restrict__ tW,
    float4* __restrict__ O)
{
    __shared__ float4 sWM[HALF * 4];   // 8 KB

    const int tid = threadIdx.x;
    const int h   = blockIdx.x & 1;           // which half of N_IN
    const int g   = blockIdx.x >> 1;          // batch group

    // ---- prologue: build 128 WM matrices (threads 0..127) ----
    if (tid < HALF) {
        const int n = h * HALF + tid;

        float a  = aW[n];
        float ux = 1.0f / (1.0f + expf(-uW[n * 3 + 0]));
        float uy = 1.0f / (1.0f + expf(-uW[n * 3 + 1]));
        float uz = 1.0f / (1.0f + expf(-uW[n * 3 + 2]));
        float inv = rsqrtf(ux * ux + uy * uy + uz * uz);
        ux *= inv; uy *= inv; uz *= inv;

        float s, c;
        __sincosf(a, &s, &c);
        // refine with accurate versions (cheap, once per matrix)
        s = sinf(a);
        c = cosf(a);

        float r00 = (1.0f - ux * ux) * c + ux * ux;
        float r01 = -uz * s - ux * uy * c + ux * uy;
        float r02 =  uy * s - ux * uz * c + ux * uz;
        float r10 =  uz * s - ux * uy * c + ux * uy;
        float r11 = (1.0f - uy * uy) * c + uy * uy;
        float r12 = -ux * s - uy * uz * c + uy * uz;
        float r20 = -uy * s - ux * uz * c + ux * uz;
        float r21 =  ux * s - uy * uz * c + uy * uz;
        float r22 = (1.0f - uz * uz) * c + uz * uz;

        float t0 = tW[n * 3 + 0];
        float t1 = tW[n * 3 + 1];
        float t2 = tW[n * 3 + 2];

        sWM[tid * 4 + 0] = make_float4(r00, r01, r02, t0);
        sWM[tid * 4 + 1] = make_float4(r10, r11, r12, t1);
        sWM[tid * 4 + 2] = make_float4(r20, r21, r22, t2);
        sWM[tid * 4 + 3] = make_float4(0.0f, 0.0f, 0.0f, 1.0f);
    }
    __syncthreads();

    // ---- cache this thread's WM rows in registers ----
    const int nloc = tid >> 2;
    const float4 r0 = sWM[nloc * 4 + 0];
    const float4 r1 = sWM[nloc * 4 + 1];
    const float4 r2 = sWM[nloc * 4 + 2];
    const float4 r3 = sWM[nloc * 4 + 3];

    // ---- stream ITER batches ----
    // float4 row index for batch b: b*1024 + h*512 + tid
    int idx = g * (ITER * N_IN * 4) + h * TPB + tid;

#pragma unroll
    for (int j = 0; j < ITER; j++) {
        float4 v = I[idx];
        float4 o;
        o.x = fmaf(v.x, r0.x, fmaf(v.y, r1.x, fmaf(v.z, r2.x, v.w * r3.x)));
        o.y = fmaf(v.x, r0.y, fmaf(v.y, r1.y, fmaf(v.z, r2.y, v.w * r3.y)));
        o.z = fmaf(v.x, r0.z, fmaf(v.y, r1.z, fmaf(v.z, r2.z, v.w * r3.z)));
        o.w = fmaf(v.x, r0.w, fmaf(v.y, r1.w, fmaf(v.z, r2.w, v.w * r3.w)));
        O[idx] = o;
        idx += N_IN * 4;
    }
}

extern "C" void kernel_launch(void* const* d_in, const int* in_sizes, int n_in,
                              void* d_out, int out_size) {
    const float* I  = (const float*)d_in[0];
    const float* aW = (const float*)d_in[1];
    const float* uW = (const float*)d_in[2];
    const float* tW = (const float*)d_in[3];

    int blocks = (BATCH / ITER) * 2;   // 1024
    fused_kernel<<<blocks, TPB>>>((const float4*)I, aW, uW, tW, (float4*)d_out);
}

// round 3
// speedup vs baseline: 1.3832x; 1.3511x over previous
#include <cuda_runtime.h>

constexpr int N_IN  = 256;
constexpr int BATCH = 4096;
constexpr int ITER  = 16;
constexpr int TPB   = 512;           // 128 matrices * 4 rows per block
constexpr int HALF  = 128;           // matrices per block half

__global__ void __launch_bounds__(TPB) fused_kernel(
    const float4* __restrict__ I,
    const float*  __restrict__ aW,
    const float*  __restrict__ uW,
    const float*  __restrict__ tW,
    float4* __restrict__ O)
{
    const int tid = threadIdx.x;
    const int h   = blockIdx.x & 1;           // which half of N_IN
    const int g   = blockIdx.x >> 1;          // batch group

    // ---- every thread builds its full WM[n] in registers (no smem, no sync) ----
    const int n = h * HALF + (tid >> 2);

    float a  = aW[n];
    float ux = 1.0f / (1.0f + expf(-uW[n * 3 + 0]));
    float uy = 1.0f / (1.0f + expf(-uW[n * 3 + 1]));
    float uz = 1.0f / (1.0f + expf(-uW[n * 3 + 2]));
    float inv = rsqrtf(ux * ux + uy * uy + uz * uz);
    ux *= inv; uy *= inv; uz *= inv;

    float s = sinf(a);
    float c = cosf(a);

    float4 r0, r1, r2, r3;
    r0.x = (1.0f - ux * ux) * c + ux * ux;
    r0.y = -uz * s - ux * uy * c + ux * uy;
    r0.z =  uy * s - ux * uz * c + ux * uz;
    r0.w = tW[n * 3 + 0];
    r1.x =  uz * s - ux * uy * c + ux * uy;
    r1.y = (1.0f - uy * uy) * c + uy * uy;
    r1.z = -ux * s - uy * uz * c + uy * uz;
    r1.w = tW[n * 3 + 1];
    r2.x = -uy * s - ux * uz * c + ux * uz;
    r2.y =  ux * s - uy * uz * c + uy * uz;
    r2.z = (1.0f - uz * uz) * c + uz * uz;
    r2.w = tW[n * 3 + 2];
    r3 = make_float4(0.0f, 0.0f, 0.0f, 1.0f);

    // out_row = v.x*r0 + v.y*r1 + v.z*r2 + v.w*r3  (rows of WM)
    // note: o.w = v.x*r0.w.. uses translation column; r3 row = (0,0,0,1)
    // o = v.x*col? No: o_j = sum_k v_k * WM[k][j]; WM rows are r0..r3.

    // ---- stream ITER batches, MLP=4 front-batched ----
    constexpr int STRIDE = N_IN * 4;           // 1024 float4 per batch
    int idx = g * (ITER * STRIDE) + h * TPB + tid;

#pragma unroll
    for (int jj = 0; jj < ITER / 4; jj++) {
        float4 v0 = I[idx];
        float4 v1 = I[idx + STRIDE];
        float4 v2 = I[idx + 2 * STRIDE];
        float4 v3 = I[idx + 3 * STRIDE];

        float4 o;
        o.x = fmaf(v0.x, r0.x, fmaf(v0.y, r1.x, fmaf(v0.z, r2.x, v0.w * r3.x)));
        o.y = fmaf(v0.x, r0.y, fmaf(v0.y, r1.y, fmaf(v0.z, r2.y, v0.w * r3.y)));
        o.z = fmaf(v0.x, r0.z, fmaf(v0.y, r1.z, fmaf(v0.z, r2.z, v0.w * r3.z)));
        o.w = fmaf(v0.x, r0.w, fmaf(v0.y, r1.w, fmaf(v0.z, r2.w, v0.w * r3.w)));
        __stcs(&O[idx], o);

        o.x = fmaf(v1.x, r0.x, fmaf(v1.y, r1.x, fmaf(v1.z, r2.x, v1.w * r3.x)));
        o.y = fmaf(v1.x, r0.y, fmaf(v1.y, r1.y, fmaf(v1.z, r2.y, v1.w * r3.y)));
        o.z = fmaf(v1.x, r0.z, fmaf(v1.y, r1.z, fmaf(v1.z, r2.z, v1.w * r3.z)));
        o.w = fmaf(v1.x, r0.w, fmaf(v1.y, r1.w, fmaf(v1.z, r2.w, v1.w * r3.w)));
        __stcs(&O[idx + STRIDE], o);

        o.x = fmaf(v2.x, r0.x, fmaf(v2.y, r1.x, fmaf(v2.z, r2.x, v2.w * r3.x)));
        o.y = fmaf(v2.x, r0.y, fmaf(v2.y, r1.y, fmaf(v2.z, r2.y, v2.w * r3.y)));
        o.z = fmaf(v2.x, r0.z, fmaf(v2.y, r1.z, fmaf(v2.z, r2.z, v2.w * r3.z)));
        o.w = fmaf(v2.x, r0.w, fmaf(v2.y, r1.w, fmaf(v2.z, r2.w, v2.w * r3.w)));
        __stcs(&O[idx + 2 * STRIDE], o);

        o.x = fmaf(v3.x, r0.x, fmaf(v3.y, r1.x, fmaf(v3.z, r2.x, v3.w * r3.x)));
        o.y = fmaf(v3.x, r0.y, fmaf(v3.y, r1.y, fmaf(v3.z, r2.y, v3.w * r3.y)));
        o.z = fmaf(v3.x, r0.z, fmaf(v3.y, r1.z, fmaf(v3.z, r2.z, v3.w * r3.z)));
        o.w = fmaf(v3.x, r0.w, fmaf(v3.y, r1.w, fmaf(v3.z, r2.w, v3.w * r3.w)));
        __stcs(&O[idx + 3 * STRIDE], o);

        idx += 4 * STRIDE;
    }
}

extern "C" void kernel_launch(void* const* d_in, const int* in_sizes, int n_in,
                              void* d_out, int out_size) {
    const float* I  = (const float*)d_in[0];
    const float* aW = (const float*)d_in[1];
    const float* uW = (const float*)d_in[2];
    const float* tW = (const float*)d_in[3];

    int blocks = (BATCH / ITER) * 2;   // 512
    fused_kernel<<<blocks, TPB>>>((const float4*)I, aW, uW, tW, (float4*)d_out);
}

// round 5
// speedup vs baseline: 1.4404x; 1.0413x over previous
#include <cuda_runtime.h>
#include <cstdint>

constexpr int N_IN  = 256;
constexpr int BATCH = 4096;
constexpr int ITER  = 16;
constexpr int TPB   = 256;   // 128 matrices * 2 row-pairs per block
constexpr int HALF  = 128;   // matrices per block

struct V8 { uint32_t r[8]; };

__device__ __forceinline__ V8 ldg256_el(const void* p) {
    V8 v;
    asm volatile("ld.global.nc.L2::evict_last.v8.b32 {%0,%1,%2,%3,%4,%5,%6,%7}, [%8];"
                 : "=r"(v.r[0]), "=r"(v.r[1]), "=r"(v.r[2]), "=r"(v.r[3]),
                   "=r"(v.r[4]), "=r"(v.r[5]), "=r"(v.r[6]), "=r"(v.r[7])
                 : "l"(p));
    return v;
}
__device__ __forceinline__ void stg256_ef(void* p, const V8& v) {
    asm volatile("st.global.L2::evict_first.v8.b32 [%0], {%1,%2,%3,%4,%5,%6,%7,%8};"
                 :: "l"(p),
                    "r"(v.r[0]), "r"(v.r[1]), "r"(v.r[2]), "r"(v.r[3]),
                    "r"(v.r[4]), "r"(v.r[5]), "r"(v.r[6]), "r"(v.r[7])
                 : "memory");
}

__global__ void __launch_bounds__(TPB) fused_kernel(
    const float* __restrict__ I,
    const float* __restrict__ aW,
    const float* __restrict__ uW,
    const float* __restrict__ tW,
    float* __restrict__ O)
{
    const int tid = threadIdx.x;
    const int h   = blockIdx.x & 1;           // which half of N_IN
    const int g   = blockIdx.x >> 1;          // batch group (0..255)

    // ---- every thread builds its WM[n] in registers (no smem, no sync) ----
    const int n = h * HALF + (tid >> 1);

    float a  = aW[n];
    float ux = 1.0f / (1.0f + expf(-uW[n * 3 + 0]));
    float uy = 1.0f / (1.0f + expf(-uW[n * 3 + 1]));
    float uz = 1.0f / (1.0f + expf(-uW[n * 3 + 2]));
    float inv = rsqrtf(ux * ux + uy * uy + uz * uz);
    ux *= inv; uy *= inv; uz *= inv;

    float s = sinf(a);
    float c = cosf(a);

    float4 r0, r1, r2, r3;
    r0.x = (1.0f - ux * ux) * c + ux * ux;
    r0.y = -uz * s - ux * uy * c + ux * uy;
    r0.z =  uy * s - ux * uz * c + ux * uz;
    r0.w = tW[n * 3 + 0];
    r1.x =  uz * s - ux * uy * c + ux * uy;
    r1.y = (1.0f - uy * uy) * c + uy * uy;
    r1.z = -ux * s - uy * uz * c + uy * uz;
    r1.w = tW[n * 3 + 1];
    r2.x = -uy * s - ux * uz * c + ux * uz;
    r2.y =  ux * s - uy * uz * c + uy * uz;
    r2.z = (1.0f - uz * uz) * c + uz * uz;
    r2.w = tW[n * 3 + 2];
    r3 = make_float4(0.0f, 0.0f, 0.0f, 1.0f);

    // ---- stream ITER batches, one 32B load/store per iteration, MLP=4 ----
    // float index of this thread's 8-float chunk within a batch:
    //   n*16 + (tid&1)*8   (rows 2p, 2p+1 of matrix n)
    constexpr int STRIDE_F = N_IN * 16;        // 4096 floats per batch
    int fidx = g * (ITER * STRIDE_F) + n * 16 + (tid & 1) * 8;

#pragma unroll
    for (int jj = 0; jj < ITER / 4; jj++) {
        V8 a0 = ldg256_el(I + fidx);
        V8 a1 = ldg256_el(I + fidx + STRIDE_F);
        V8 a2 = ldg256_el(I + fidx + 2 * STRIDE_F);
        V8 a3 = ldg256_el(I + fidx + 3 * STRIDE_F);

        V8 in[4] = {a0, a1, a2, a3};
#pragma unroll
        for (int k = 0; k < 4; k++) {
            V8 ov;
#pragma unroll
            for (int half = 0; half < 2; half++) {
                float vx = __uint_as_float(in[k].r[half * 4 + 0]);
                float vy = __uint_as_float(in[k].r[half * 4 + 1]);
                float vz = __uint_as_float(in[k].r[half * 4 + 2]);
                float vw = __uint_as_float(in[k].r[half * 4 + 3]);
                float ox = fmaf(vx, r0.x, fmaf(vy, r1.x, fmaf(vz, r2.x, vw * r3.x)));
                float oy = fmaf(vx, r0.y, fmaf(vy, r1.y, fmaf(vz, r2.y, vw * r3.y)));
                float oz = fmaf(vx, r0.z, fmaf(vy, r1.z, fmaf(vz, r2.z, vw * r3.z)));
                float ow = fmaf(vx, r0.w, fmaf(vy, r1.w, fmaf(vz, r2.w, vw * r3.w)));
                ov.r[half * 4 + 0] = __float_as_uint(ox);
                ov.r[half * 4 + 1] = __float_as_uint(oy);
                ov.r[half * 4 + 2] = __float_as_uint(oz);
                ov.r[half * 4 + 3] = __float_as_uint(ow);
            }
            stg256_ef(O + fidx + k * STRIDE_F, ov);
        }
        fidx += 4 * STRIDE_F;
    }
}

extern "C" void kernel_launch(void* const* d_in, const int* in_sizes, int n_in,
                              void* d_out, int out_size) {
    const float* I  = (const float*)d_in[0];
    const float* aW = (const float*)d_in[1];
    const float* uW = (const float*)d_in[2];
    const float* tW = (const float*)d_in[3];

    int blocks = (BATCH / ITER) * 2;   // 512
    fused_kernel<<<blocks, TPB>>>(I, aW, uW, tW, (float*)d_out);
}